// round 4
// baseline (speedup 1.0000x reference)
#include <cuda_runtime.h>
#include <math.h>

// Problem constants
#define BATCH  8
#define SEQ    1024
#define DMODEL 1024
#define HEADS  16
#define HDIM   64
#define MTOT   (BATCH * SEQ)          // 8192

// -------------------- scratch (__device__ globals; no allocs allowed) -------
__device__ float g_q[(size_t)BATCH * HEADS * SEQ * HDIM];   // [B,H,S,Hd]
__device__ float g_k[(size_t)BATCH * HEADS * SEQ * HDIM];
__device__ float g_v[(size_t)BATCH * HEADS * SEQ * HDIM];
__device__ float g_ctx[(size_t)BATCH * SEQ * DMODEL];       // [B,S,D]

// -------------------- TF32 mma.sync helpers ---------------------------------
__device__ __forceinline__ unsigned f2tf(float f) {
    unsigned u;
    asm("cvt.rna.tf32.f32 %0, %1;" : "=r"(u) : "f"(f));
    return u;
}

// D = A(16x8, row) * B(8x8, col) + D, tf32 inputs, fp32 accum
__device__ __forceinline__ void mma8(float* c, const unsigned* a, const unsigned* b) {
    asm volatile(
        "mma.sync.aligned.m16n8k8.row.col.f32.tf32.tf32.f32 "
        "{%0,%1,%2,%3}, {%4,%5,%6,%7}, {%8,%9}, {%0,%1,%2,%3};\n"
        : "+f"(c[0]), "+f"(c[1]), "+f"(c[2]), "+f"(c[3])
        : "r"(a[0]), "r"(a[1]), "r"(a[2]), "r"(a[3]), "r"(b[0]), "r"(b[1]));
}

// =============================================================================
// Projection GEMM: C[M,1024] = A[M,1024] * W[1024,1024]^T + bias
// BM=128, BN=128, BK=32; 8 warps, warp tile 64x32 (2x4 warp grid).
// Double-buffered smem + register prefetch.
// =============================================================================
#define PSTR 36            // 36 % 32 == 4 -> conflict-free frags
#define PBUF (128 * PSTR)  // one stage (unsigned)
#define PROJ_SMEM_BYTES (4 * PBUF * 4)   // 2 stages x (A,B)

__global__ __launch_bounds__(256)
void proj_tf32_kernel(const float* __restrict__ A, const float* __restrict__ W,
                      const float* __restrict__ bias, float* __restrict__ C,
                      int split_heads)
{
    extern __shared__ unsigned psm[];
    unsigned* As = psm;              // [2][PBUF]
    unsigned* Bs = psm + 2 * PBUF;   // [2][PBUF]

    const int tid  = threadIdx.x;
    const int wid  = tid >> 5;
    const int lane = tid & 31;
    const int gid  = lane >> 2;   // 0..7
    const int tig  = lane & 3;    // 0..3
    const int m0 = blockIdx.y * 128;
    const int n0 = blockIdx.x * 128;
    const int wm = (wid >> 2) * 64;   // 0 or 64
    const int wn = (wid & 3) * 32;    // 0..96

    // per-thread load coords (fixed across tiles)
    const int lrow = tid >> 3;            // 0..31 (+32*r)
    const int lc4  = (tid & 7) * 4;       // 0..28

    float acc[4][4][4];
#pragma unroll
    for (int mt = 0; mt < 4; mt++)
#pragma unroll
        for (int nt = 0; nt < 4; nt++)
#pragma unroll
            for (int r = 0; r < 4; r++) acc[mt][nt][r] = 0.0f;

    float4 aR[4], wR[4];
    // prologue: LDG tile 0
#pragma unroll
    for (int r = 0; r < 4; r++) {
        int row = lrow + r * 32;
        aR[r] = *(const float4*)(A + (size_t)(m0 + row) * DMODEL + lc4);
        wR[r] = *(const float4*)(W + (size_t)(n0 + row) * DMODEL + lc4);
    }
    // STS tile 0 -> buf 0
#pragma unroll
    for (int r = 0; r < 4; r++) {
        int row = lrow + r * 32;
        unsigned* d = &As[row * PSTR + lc4];
        d[0] = f2tf(aR[r].x); d[1] = f2tf(aR[r].y); d[2] = f2tf(aR[r].z); d[3] = f2tf(aR[r].w);
        unsigned* e = &Bs[row * PSTR + lc4];
        e[0] = f2tf(wR[r].x); e[1] = f2tf(wR[r].y); e[2] = f2tf(wR[r].z); e[3] = f2tf(wR[r].w);
    }

    int buf = 0;
    for (int kt = 0; kt < DMODEL; kt += 32) {
        __syncthreads();
        const int more = (kt + 32 < DMODEL);
        if (more) {
#pragma unroll
            for (int r = 0; r < 4; r++) {
                int row = lrow + r * 32;
                aR[r] = *(const float4*)(A + (size_t)(m0 + row) * DMODEL + kt + 32 + lc4);
                wR[r] = *(const float4*)(W + (size_t)(n0 + row) * DMODEL + kt + 32 + lc4);
            }
        }

        const unsigned* Ab = &As[buf * PBUF];
        const unsigned* Bb = &Bs[buf * PBUF];
#pragma unroll
        for (int ks = 0; ks < 4; ks++) {
            unsigned af[4][4], bf[4][2];
#pragma unroll
            for (int mt = 0; mt < 4; mt++) {
                const unsigned* p  = &Ab[(wm + mt * 16 + gid) * PSTR + ks * 8 + tig];
                const unsigned* p2 = p + 8 * PSTR;
                af[mt][0] = p[0];  af[mt][2] = p[4];
                af[mt][1] = p2[0]; af[mt][3] = p2[4];
            }
#pragma unroll
            for (int nt = 0; nt < 4; nt++) {
                const unsigned* p = &Bb[(wn + nt * 8 + gid) * PSTR + ks * 8 + tig];
                bf[nt][0] = p[0]; bf[nt][1] = p[4];
            }
#pragma unroll
            for (int mt = 0; mt < 4; mt++)
#pragma unroll
                for (int nt = 0; nt < 4; nt++)
                    mma8(acc[mt][nt], af[mt], bf[nt]);
        }

        if (more) {
            unsigned* An = &As[(buf ^ 1) * PBUF];
            unsigned* Bn = &Bs[(buf ^ 1) * PBUF];
#pragma unroll
            for (int r = 0; r < 4; r++) {
                int row = lrow + r * 32;
                unsigned* d = &An[row * PSTR + lc4];
                d[0] = f2tf(aR[r].x); d[1] = f2tf(aR[r].y); d[2] = f2tf(aR[r].z); d[3] = f2tf(aR[r].w);
                unsigned* e = &Bn[row * PSTR + lc4];
                e[0] = f2tf(wR[r].x); e[1] = f2tf(wR[r].y); e[2] = f2tf(wR[r].z); e[3] = f2tf(wR[r].w);
            }
        }
        buf ^= 1;
    }

    // epilogue
#pragma unroll
    for (int mt = 0; mt < 4; mt++) {
#pragma unroll
        for (int half = 0; half < 2; half++) {
            int m  = m0 + wm + mt * 16 + gid + half * 8;
            int bb = m >> 10;
            int s  = m & 1023;
#pragma unroll
            for (int nt = 0; nt < 4; nt++) {
                int n = n0 + wn + nt * 8 + tig * 2;
                float2 v;
                v.x = acc[mt][nt][half * 2 + 0] + bias[n];
                v.y = acc[mt][nt][half * 2 + 1] + bias[n + 1];
                size_t idx;
                if (split_heads) {
                    int h = n >> 6, d = n & 63;
                    idx = ((((size_t)bb * HEADS + h) * SEQ + s) << 6) + d;
                } else {
                    idx = (size_t)m * DMODEL + n;
                }
                *(float2*)(C + idx) = v;
            }
        }
    }
}

// =============================================================================
// Fused scores + softmax: one block = 32 query rows x all 1024 keys for (b,h).
// Score strip lives in smem; softmax in place; final attn written once.
// Warp n-split: warp w computes cols [kt*128 + w*16, +16) per k-tile.
// =============================================================================
#define FSTR 1032            // strip row stride (floats)
#define QSTR 68              // tf32 tile strides (==4 mod 32)
#define STRIP_FLOATS (32 * FSTR)
#define QS_U (32 * QSTR)
#define KS_U (128 * QSTR)
#define FUSED_SMEM_BYTES ((STRIP_FLOATS + QS_U + 2 * KS_U) * 4)

__global__ __launch_bounds__(256)
void attn_fused_kernel(const float* __restrict__ q, const float* __restrict__ k,
                       float* __restrict__ attn)
{
    extern __shared__ float dsm[];
    float*    strip = dsm;                                   // [32][FSTR]
    unsigned* Qs = (unsigned*)(dsm + STRIP_FLOATS);          // [32][QSTR]
    unsigned* Ks = (unsigned*)(dsm + STRIP_FLOATS + QS_U);   // [2][128][QSTR]

    const int tid  = threadIdx.x;
    const int wid  = tid >> 5;
    const int lane = tid & 31;
    const int gid  = lane >> 2;
    const int tig  = lane & 3;
    const int bh = blockIdx.y;
    const int q0 = blockIdx.x * 32;

    const float* qb = q + ((size_t)bh * SEQ + q0) * HDIM;
    const float* kb = k + (size_t)bh * SEQ * HDIM;

    // load Q (32x64) -> tf32 smem
#pragma unroll
    for (int r = 0; r < 2; r++) {
        int idx = tid + r * 256;        // 0..511
        int row = idx >> 4;             // 0..31
        int c4  = (idx & 15) * 4;       // 0..60
        float4 a4 = *(const float4*)(qb + (size_t)row * HDIM + c4);
        unsigned* d = &Qs[row * QSTR + c4];
        d[0] = f2tf(a4.x); d[1] = f2tf(a4.y); d[2] = f2tf(a4.z); d[3] = f2tf(a4.w);
    }

    // K tile prologue (tile 0): 128x64, 8 float4/thread
    const int krow = tid >> 4;           // with +16*r? no: idx>>4 below
    float4 kreg[8];
#pragma unroll
    for (int r = 0; r < 8; r++) {
        int idx = tid + r * 256;         // 0..2047
        int row = idx >> 4;              // 0..127
        int c4  = (idx & 15) * 4;
        kreg[r] = *(const float4*)(kb + (size_t)row * HDIM + c4);
    }
#pragma unroll
    for (int r = 0; r < 8; r++) {
        int idx = tid + r * 256;
        int row = idx >> 4;
        int c4  = (idx & 15) * 4;
        unsigned* d = &Ks[row * QSTR + c4];
        d[0] = f2tf(kreg[r].x); d[1] = f2tf(kreg[r].y);
        d[2] = f2tf(kreg[r].z); d[3] = f2tf(kreg[r].w);
    }
    (void)krow;

    int buf = 0;
    for (int kt = 0; kt < 8; kt++) {
        __syncthreads();
        const int more = (kt < 7);
        if (more) {
#pragma unroll
            for (int r = 0; r < 8; r++) {
                int idx = tid + r * 256;
                int row = idx >> 4;
                int c4  = (idx & 15) * 4;
                kreg[r] = *(const float4*)(kb + ((size_t)(kt + 1) * 128 + row) * HDIM + c4);
            }
        }

        const unsigned* Kb = &Ks[buf * KS_U];
        float acc[2][2][4];
#pragma unroll
        for (int mt = 0; mt < 2; mt++)
#pragma unroll
            for (int nt = 0; nt < 2; nt++)
#pragma unroll
                for (int r = 0; r < 4; r++) acc[mt][nt][r] = 0.0f;

#pragma unroll
        for (int ks = 0; ks < 8; ks++) {
            unsigned af[2][4], bf[2][2];
#pragma unroll
            for (int mt = 0; mt < 2; mt++) {
                const unsigned* p  = &Qs[(mt * 16 + gid) * QSTR + ks * 8 + tig];
                const unsigned* p2 = p + 8 * QSTR;
                af[mt][0] = p[0];  af[mt][2] = p[4];
                af[mt][1] = p2[0]; af[mt][3] = p2[4];
            }
#pragma unroll
            for (int nt = 0; nt < 2; nt++) {
                const unsigned* p = &Kb[(wid * 16 + nt * 8 + gid) * QSTR + ks * 8 + tig];
                bf[nt][0] = p[0]; bf[nt][1] = p[4];
            }
#pragma unroll
            for (int mt = 0; mt < 2; mt++)
#pragma unroll
                for (int nt = 0; nt < 2; nt++)
                    mma8(acc[mt][nt], af[mt], bf[nt]);
        }

        // write scaled scores into strip
#pragma unroll
        for (int mt = 0; mt < 2; mt++)
#pragma unroll
            for (int half = 0; half < 2; half++) {
                int row = mt * 16 + gid + half * 8;
#pragma unroll
                for (int nt = 0; nt < 2; nt++) {
                    int col = kt * 128 + wid * 16 + nt * 8 + tig * 2;
                    float2 v;
                    v.x = acc[mt][nt][half * 2 + 0] * 0.125f;
                    v.y = acc[mt][nt][half * 2 + 1] * 0.125f;
                    *(float2*)&strip[row * FSTR + col] = v;
                }
            }

        if (more) {
            unsigned* Kn = &Ks[(buf ^ 1) * KS_U];
#pragma unroll
            for (int r = 0; r < 8; r++) {
                int idx = tid + r * 256;
                int row = idx >> 4;
                int c4  = (idx & 15) * 4;
                unsigned* d = &Kn[row * QSTR + c4];
                d[0] = f2tf(kreg[r].x); d[1] = f2tf(kreg[r].y);
                d[2] = f2tf(kreg[r].z); d[3] = f2tf(kreg[r].w);
            }
        }
        buf ^= 1;
    }
    __syncthreads();

    // ---- softmax over strip rows; write final attn ----
#pragma unroll
    for (int ri = 0; ri < 4; ri++) {
        int r = wid * 4 + ri;
        float* row = &strip[r * FSTR];
        float4 v[8];
        float mx = -1e30f;
#pragma unroll
        for (int i = 0; i < 8; i++) {
            v[i] = *(float4*)&row[(i * 32 + lane) * 4];
            mx = fmaxf(mx, fmaxf(fmaxf(v[i].x, v[i].y), fmaxf(v[i].z, v[i].w)));
        }
#pragma unroll
        for (int off = 16; off > 0; off >>= 1)
            mx = fmaxf(mx, __shfl_xor_sync(0xffffffffu, mx, off));
        float sum = 0.0f;
#pragma unroll
        for (int i = 0; i < 8; i++) {
            v[i].x = __expf(v[i].x - mx);
            v[i].y = __expf(v[i].y - mx);
            v[i].z = __expf(v[i].z - mx);
            v[i].w = __expf(v[i].w - mx);
            sum += v[i].x + v[i].y + v[i].z + v[i].w;
        }
#pragma unroll
        for (int off = 16; off > 0; off >>= 1)
            sum += __shfl_xor_sync(0xffffffffu, sum, off);
        float inv = 1.0f / sum;
        float4* arow = (float4*)(attn + ((size_t)bh * SEQ + q0 + r) * SEQ);
#pragma unroll
        for (int i = 0; i < 8; i++) {
            v[i].x *= inv; v[i].y *= inv; v[i].z *= inv; v[i].w *= inv;
            arow[i * 32 + lane] = v[i];
        }
    }
}

// =============================================================================
// Context GEMM: ctx[q,d] = sum_k P[q,k] * V[k,d] per (b,h).
// BM=256, N=64, BK=32; 8 warps, warp tile 32x64. Double-buffered + prefetch.
// =============================================================================
#define CSTR 36
#define VSTR 72
#define CP_U (256 * CSTR)
#define CV_U (32 * VSTR)
#define CTX_SMEM_BYTES ((2 * CP_U + 2 * CV_U) * 4)

__global__ __launch_bounds__(256)
void ctx_tf32_kernel(const float* __restrict__ attn, const float* __restrict__ v,
                     float* __restrict__ ctx)
{
    extern __shared__ unsigned csm[];
    unsigned* Ps = csm;               // [2][CP_U]
    unsigned* Vs = csm + 2 * CP_U;    // [2][CV_U]

    const int tid  = threadIdx.x;
    const int wid  = tid >> 5;
    const int lane = tid & 31;
    const int gid  = lane >> 2;
    const int tig  = lane & 3;
    const int bh = blockIdx.y;
    const int q0 = blockIdx.x * 256;
    const int b = bh >> 4, h = bh & 15;

    const float* pb = attn + (size_t)bh * SEQ * SEQ;
    const float* vb = v + (size_t)bh * SEQ * HDIM;

    const int prow = tid >> 3;            // 0..31 (+32*r)
    const int pc4  = (tid & 7) * 4;
    const int vrow = tid >> 4;            // 0..15 (+16*r)
    const int vc4  = (tid & 15) * 4;

    float acc[2][8][4];
#pragma unroll
    for (int mt = 0; mt < 2; mt++)
#pragma unroll
        for (int nt = 0; nt < 8; nt++)
#pragma unroll
            for (int r = 0; r < 4; r++) acc[mt][nt][r] = 0.0f;

    float4 p4[8], v4[2];
    // prologue LDG tile 0
#pragma unroll
    for (int r = 0; r < 8; r++)
        p4[r] = *(const float4*)(pb + (size_t)(q0 + prow + r * 32) * SEQ + pc4);
#pragma unroll
    for (int r = 0; r < 2; r++)
        v4[r] = *(const float4*)(vb + (size_t)(vrow + r * 16) * HDIM + vc4);
    // STS -> buf0
#pragma unroll
    for (int r = 0; r < 8; r++) {
        unsigned* d = &Ps[(prow + r * 32) * CSTR + pc4];
        d[0] = f2tf(p4[r].x); d[1] = f2tf(p4[r].y); d[2] = f2tf(p4[r].z); d[3] = f2tf(p4[r].w);
    }
#pragma unroll
    for (int r = 0; r < 2; r++) {
        unsigned* e = &Vs[(vrow + r * 16) * VSTR + vc4];
        e[0] = f2tf(v4[r].x); e[1] = f2tf(v4[r].y); e[2] = f2tf(v4[r].z); e[3] = f2tf(v4[r].w);
    }

    int buf = 0;
    for (int kt = 0; kt < SEQ; kt += 32) {
        __syncthreads();
        const int more = (kt + 32 < SEQ);
        if (more) {
#pragma unroll
            for (int r = 0; r < 8; r++)
                p4[r] = *(const float4*)(pb + (size_t)(q0 + prow + r * 32) * SEQ + kt + 32 + pc4);
#pragma unroll
            for (int r = 0; r < 2; r++)
                v4[r] = *(const float4*)(vb + (size_t)(kt + 32 + vrow + r * 16) * HDIM + vc4);
        }

        const unsigned* Pb = &Ps[buf * CP_U];
        const unsigned* Vb = &Vs[buf * CV_U];
#pragma unroll
        for (int ks = 0; ks < 4; ks++) {
            unsigned af[2][4], bf[8][2];
#pragma unroll
            for (int mt = 0; mt < 2; mt++) {
                const unsigned* p  = &Pb[(wid * 32 + mt * 16 + gid) * CSTR + ks * 8 + tig];
                const unsigned* p2 = p + 8 * CSTR;
                af[mt][0] = p[0];  af[mt][2] = p[4];
                af[mt][1] = p2[0]; af[mt][3] = p2[4];
            }
#pragma unroll
            for (int nt = 0; nt < 8; nt++) {
                const unsigned* p = &Vb[(ks * 8 + tig) * VSTR + nt * 8 + gid];
                bf[nt][0] = p[0]; bf[nt][1] = p[4 * VSTR];
            }
#pragma unroll
            for (int mt = 0; mt < 2; mt++)
#pragma unroll
                for (int nt = 0; nt < 8; nt++)
                    mma8(acc[mt][nt], af[mt], bf[nt]);
        }

        if (more) {
            unsigned* Pn = &Ps[(buf ^ 1) * CP_U];
            unsigned* Vn = &Vs[(buf ^ 1) * CV_U];
#pragma unroll
            for (int r = 0; r < 8; r++) {
                unsigned* d = &Pn[(prow + r * 32) * CSTR + pc4];
                d[0] = f2tf(p4[r].x); d[1] = f2tf(p4[r].y); d[2] = f2tf(p4[r].z); d[3] = f2tf(p4[r].w);
            }
#pragma unroll
            for (int r = 0; r < 2; r++) {
                unsigned* e = &Vn[(vrow + r * 16) * VSTR + vc4];
                e[0] = f2tf(v4[r].x); e[1] = f2tf(v4[r].y); e[2] = f2tf(v4[r].z); e[3] = f2tf(v4[r].w);
            }
        }
        buf ^= 1;
    }

#pragma unroll
    for (int mt = 0; mt < 2; mt++) {
#pragma unroll
        for (int half = 0; half < 2; half++) {
            int qrow = q0 + wid * 32 + mt * 16 + gid + half * 8;
            float* crow = ctx + ((size_t)b * SEQ + qrow) * DMODEL + h * HDIM;
#pragma unroll
            for (int nt = 0; nt < 8; nt++) {
                int d = nt * 8 + tig * 2;
                float2 o;
                o.x = acc[mt][nt][half * 2 + 0];
                o.y = acc[mt][nt][half * 2 + 1];
                *(float2*)(crow + d) = o;
            }
        }
    }
}

// -------------------- launcher ----------------------------------------------
extern "C" void kernel_launch(void* const* d_in, const int* in_sizes, int n_in,
                              void* d_out, int out_size)
{
    const float* x  = (const float*)d_in[0];
    const float* Wq = (const float*)d_in[1];
    const float* bq = (const float*)d_in[2];
    const float* Wk = (const float*)d_in[3];
    const float* bk = (const float*)d_in[4];
    const float* Wv = (const float*)d_in[5];
    const float* bv = (const float*)d_in[6];
    const float* Wo = (const float*)d_in[7];
    const float* bo = (const float*)d_in[8];

    float* out_ptr  = (float*)d_out;                                   // [B,S,D]
    float* attn_ptr = (float*)d_out + (size_t)BATCH * SEQ * DMODEL;    // [B,H,S,S]

    float *qp, *kp, *vp, *cp;
    cudaGetSymbolAddress((void**)&qp, g_q);
    cudaGetSymbolAddress((void**)&kp, g_k);
    cudaGetSymbolAddress((void**)&vp, g_v);
    cudaGetSymbolAddress((void**)&cp, g_ctx);

    cudaFuncSetAttribute(proj_tf32_kernel,
                         cudaFuncAttributeMaxDynamicSharedMemorySize, PROJ_SMEM_BYTES);
    cudaFuncSetAttribute(attn_fused_kernel,
                         cudaFuncAttributeMaxDynamicSharedMemorySize, FUSED_SMEM_BYTES);
    cudaFuncSetAttribute(ctx_tf32_kernel,
                         cudaFuncAttributeMaxDynamicSharedMemorySize, CTX_SMEM_BYTES);

    dim3 blk(256);
    dim3 pgrid(DMODEL / 128, MTOT / 128);       // (8, 64)

    proj_tf32_kernel<<<pgrid, blk, PROJ_SMEM_BYTES>>>(x, Wq, bq, qp, 1);
    proj_tf32_kernel<<<pgrid, blk, PROJ_SMEM_BYTES>>>(x, Wk, bk, kp, 1);
    proj_tf32_kernel<<<pgrid, blk, PROJ_SMEM_BYTES>>>(x, Wv, bv, vp, 1);

    dim3 fgrid(SEQ / 32, BATCH * HEADS);        // (32, 128)
    attn_fused_kernel<<<fgrid, blk, FUSED_SMEM_BYTES>>>(qp, kp, attn_ptr);

    dim3 cgrid(SEQ / 256, BATCH * HEADS);       // (4, 128)
    ctx_tf32_kernel<<<cgrid, blk, CTX_SMEM_BYTES>>>(attn_ptr, vp, cp);

    proj_tf32_kernel<<<pgrid, blk, PROJ_SMEM_BYTES>>>(cp, Wo, bo, out_ptr, 0);
}

// round 5
// speedup vs baseline: 1.0066x; 1.0066x over previous
#include <cuda_runtime.h>
#include <math.h>

// Problem constants
#define BATCH  8
#define SEQ    1024
#define DMODEL 1024
#define HEADS  16
#define HDIM   64
#define MTOT   (BATCH * SEQ)          // 8192

// -------------------- scratch (__device__ globals; no allocs allowed) -------
__device__ float g_q[(size_t)BATCH * HEADS * SEQ * HDIM];   // [B,H,S,Hd]
__device__ float g_k[(size_t)BATCH * HEADS * SEQ * HDIM];
__device__ float g_v[(size_t)BATCH * HEADS * SEQ * HDIM];
__device__ float g_ctx[(size_t)BATCH * SEQ * DMODEL];       // [B,S,D]
__device__ float g_rowsum[(size_t)BATCH * HEADS * SEQ * 8]; // [row][kb] partial exp sums

// -------------------- TF32 mma.sync helpers ---------------------------------
__device__ __forceinline__ unsigned f2tf(float f) {
    unsigned u;
    asm("cvt.rna.tf32.f32 %0, %1;" : "=r"(u) : "f"(f));
    return u;
}

// D = A(16x8, row) * B(8x8, col) + D, tf32 inputs, fp32 accum
__device__ __forceinline__ void mma8(float* c, const unsigned* a, const unsigned* b) {
    asm volatile(
        "mma.sync.aligned.m16n8k8.row.col.f32.tf32.tf32.f32 "
        "{%0,%1,%2,%3}, {%4,%5,%6,%7}, {%8,%9}, {%0,%1,%2,%3};\n"
        : "+f"(c[0]), "+f"(c[1]), "+f"(c[2]), "+f"(c[3])
        : "r"(a[0]), "r"(a[1]), "r"(a[2]), "r"(a[3]), "r"(b[0]), "r"(b[1]));
}

// =============================================================================
// Projection GEMM: C[M,1024] = A[M,1024] * W[1024,1024]^T + bias
// BM=128, BN=128, BK=32; 8 warps, warp tile 64x32. Double-buffered + prefetch.
// =============================================================================
#define PSTR 36            // 36 % 32 == 4 -> conflict-free frags
#define PBUF (128 * PSTR)
#define PROJ_SMEM_BYTES (4 * PBUF * 4)

__global__ __launch_bounds__(256)
void proj_tf32_kernel(const float* __restrict__ A, const float* __restrict__ W,
                      const float* __restrict__ bias, float* __restrict__ C,
                      int split_heads)
{
    extern __shared__ unsigned psm[];
    unsigned* As = psm;              // [2][PBUF]
    unsigned* Bs = psm + 2 * PBUF;   // [2][PBUF]

    const int tid  = threadIdx.x;
    const int wid  = tid >> 5;
    const int lane = tid & 31;
    const int gid  = lane >> 2;
    const int tig  = lane & 3;
    const int m0 = blockIdx.y * 128;
    const int n0 = blockIdx.x * 128;
    const int wm = (wid >> 2) * 64;
    const int wn = (wid & 3) * 32;

    const int lrow = tid >> 3;            // 0..31 (+32*r)
    const int lc4  = (tid & 7) * 4;       // 0..28

    float acc[4][4][4];
#pragma unroll
    for (int mt = 0; mt < 4; mt++)
#pragma unroll
        for (int nt = 0; nt < 4; nt++)
#pragma unroll
            for (int r = 0; r < 4; r++) acc[mt][nt][r] = 0.0f;

    float4 aR[4], wR[4];
#pragma unroll
    for (int r = 0; r < 4; r++) {
        int row = lrow + r * 32;
        aR[r] = *(const float4*)(A + (size_t)(m0 + row) * DMODEL + lc4);
        wR[r] = *(const float4*)(W + (size_t)(n0 + row) * DMODEL + lc4);
    }
#pragma unroll
    for (int r = 0; r < 4; r++) {
        int row = lrow + r * 32;
        unsigned* d = &As[row * PSTR + lc4];
        d[0] = f2tf(aR[r].x); d[1] = f2tf(aR[r].y); d[2] = f2tf(aR[r].z); d[3] = f2tf(aR[r].w);
        unsigned* e = &Bs[row * PSTR + lc4];
        e[0] = f2tf(wR[r].x); e[1] = f2tf(wR[r].y); e[2] = f2tf(wR[r].z); e[3] = f2tf(wR[r].w);
    }

    int buf = 0;
    for (int kt = 0; kt < DMODEL; kt += 32) {
        __syncthreads();
        const int more = (kt + 32 < DMODEL);
        if (more) {
#pragma unroll
            for (int r = 0; r < 4; r++) {
                int row = lrow + r * 32;
                aR[r] = *(const float4*)(A + (size_t)(m0 + row) * DMODEL + kt + 32 + lc4);
                wR[r] = *(const float4*)(W + (size_t)(n0 + row) * DMODEL + kt + 32 + lc4);
            }
        }

        const unsigned* Ab = &As[buf * PBUF];
        const unsigned* Bb = &Bs[buf * PBUF];
#pragma unroll
        for (int ks = 0; ks < 4; ks++) {
            unsigned af[4][4], bf[4][2];
#pragma unroll
            for (int mt = 0; mt < 4; mt++) {
                const unsigned* p  = &Ab[(wm + mt * 16 + gid) * PSTR + ks * 8 + tig];
                const unsigned* p2 = p + 8 * PSTR;
                af[mt][0] = p[0];  af[mt][2] = p[4];
                af[mt][1] = p2[0]; af[mt][3] = p2[4];
            }
#pragma unroll
            for (int nt = 0; nt < 4; nt++) {
                const unsigned* p = &Bb[(wn + nt * 8 + gid) * PSTR + ks * 8 + tig];
                bf[nt][0] = p[0]; bf[nt][1] = p[4];
            }
#pragma unroll
            for (int mt = 0; mt < 4; mt++)
#pragma unroll
                for (int nt = 0; nt < 4; nt++)
                    mma8(acc[mt][nt], af[mt], bf[nt]);
        }

        if (more) {
            unsigned* An = &As[(buf ^ 1) * PBUF];
            unsigned* Bn = &Bs[(buf ^ 1) * PBUF];
#pragma unroll
            for (int r = 0; r < 4; r++) {
                int row = lrow + r * 32;
                unsigned* d = &An[row * PSTR + lc4];
                d[0] = f2tf(aR[r].x); d[1] = f2tf(aR[r].y); d[2] = f2tf(aR[r].z); d[3] = f2tf(aR[r].w);
                unsigned* e = &Bn[row * PSTR + lc4];
                e[0] = f2tf(wR[r].x); e[1] = f2tf(wR[r].y); e[2] = f2tf(wR[r].z); e[3] = f2tf(wR[r].w);
            }
        }
        buf ^= 1;
    }

#pragma unroll
    for (int mt = 0; mt < 4; mt++) {
#pragma unroll
        for (int half = 0; half < 2; half++) {
            int m  = m0 + wm + mt * 16 + gid + half * 8;
            int bb = m >> 10;
            int s  = m & 1023;
#pragma unroll
            for (int nt = 0; nt < 4; nt++) {
                int n = n0 + wn + nt * 8 + tig * 2;
                float2 v;
                v.x = acc[mt][nt][half * 2 + 0] + bias[n];
                v.y = acc[mt][nt][half * 2 + 1] + bias[n + 1];
                size_t idx;
                if (split_heads) {
                    int h = n >> 6, d = n & 63;
                    idx = ((((size_t)bb * HEADS + h) * SEQ + s) << 6) + d;
                } else {
                    idx = (size_t)m * DMODEL + n;
                }
                *(float2*)(C + idx) = v;
            }
        }
    }
}

// =============================================================================
// Scores: e = exp(Q.K/8) written UNNORMALIZED into attn region, plus per-block
// row partial sums into g_rowsum[row][kb]. Tiles 128x128, K=64, per (b,h).
// =============================================================================
#define SSTR 68   // 68 % 32 == 4 -> conflict-free
#define SCORES_SMEM_BYTES (2 * 128 * SSTR * 4)

__global__ __launch_bounds__(256)
void scores_tf32_kernel(const float* __restrict__ q, const float* __restrict__ k,
                        float* __restrict__ attn, float* __restrict__ rowsum)
{
    extern __shared__ unsigned sm[];
    unsigned* Qs = sm;                 // [128][SSTR]
    unsigned* Ks = sm + 128 * SSTR;    // [128][SSTR]
    __shared__ float sexp[128];

    const int tid  = threadIdx.x;
    const int wid  = tid >> 5;
    const int lane = tid & 31;
    const int gid  = lane >> 2;
    const int tig  = lane & 3;
    const int bh = blockIdx.z;
    const int q0 = blockIdx.y * 128;
    const int k0 = blockIdx.x * 128;
    const int kb = blockIdx.x;
    const int wm = (wid >> 2) * 64;
    const int wn = (wid & 3) * 32;

    const float* qb = q + (size_t)bh * SEQ * HDIM;
    const float* kb_ptr = k + (size_t)bh * SEQ * HDIM;

#pragma unroll
    for (int r = 0; r < 8; r++) {
        int idx = tid + r * 256;        // 0..2047
        int row = idx >> 4;             // 0..127
        int c4  = (idx & 15) * 4;       // 0..60
        float4 a4 = *(const float4*)(qb + (size_t)(q0 + row) * HDIM + c4);
        unsigned* d = &Qs[row * SSTR + c4];
        d[0] = f2tf(a4.x); d[1] = f2tf(a4.y); d[2] = f2tf(a4.z); d[3] = f2tf(a4.w);
        float4 b4 = *(const float4*)(kb_ptr + (size_t)(k0 + row) * HDIM + c4);
        unsigned* e = &Ks[row * SSTR + c4];
        e[0] = f2tf(b4.x); e[1] = f2tf(b4.y); e[2] = f2tf(b4.z); e[3] = f2tf(b4.w);
    }
    if (tid < 128) sexp[tid] = 0.0f;
    __syncthreads();

    float acc[4][4][4];
#pragma unroll
    for (int mt = 0; mt < 4; mt++)
#pragma unroll
        for (int nt = 0; nt < 4; nt++)
#pragma unroll
            for (int r = 0; r < 4; r++) acc[mt][nt][r] = 0.0f;

#pragma unroll
    for (int ks = 0; ks < 8; ks++) {
        unsigned af[4][4], bf[4][2];
#pragma unroll
        for (int mt = 0; mt < 4; mt++) {
            const unsigned* p  = &Qs[(wm + mt * 16 + gid) * SSTR + ks * 8 + tig];
            const unsigned* p2 = p + 8 * SSTR;
            af[mt][0] = p[0];  af[mt][2] = p[4];
            af[mt][1] = p2[0]; af[mt][3] = p2[4];
        }
#pragma unroll
        for (int nt = 0; nt < 4; nt++) {
            const unsigned* p = &Ks[(wn + nt * 8 + gid) * SSTR + ks * 8 + tig];
            bf[nt][0] = p[0]; bf[nt][1] = p[4];
        }
#pragma unroll
        for (int mt = 0; mt < 4; mt++)
#pragma unroll
            for (int nt = 0; nt < 4; nt++)
                mma8(acc[mt][nt], af[mt], bf[nt]);
    }

    // epilogue: e = exp(s/8); store e; accumulate per-row partial sums
    float* ab = attn + (size_t)bh * SEQ * SEQ;
#pragma unroll
    for (int mt = 0; mt < 4; mt++) {
#pragma unroll
        for (int half = 0; half < 2; half++) {
            int lr = wm + mt * 16 + gid + half * 8;     // local row 0..127
            int sq = q0 + lr;
            float lsum = 0.0f;
#pragma unroll
            for (int nt = 0; nt < 4; nt++) {
                int sk = k0 + wn + nt * 8 + tig * 2;
                float2 v;
                v.x = __expf(acc[mt][nt][half * 2 + 0] * 0.125f);
                v.y = __expf(acc[mt][nt][half * 2 + 1] * 0.125f);
                lsum += v.x + v.y;
                *(float2*)(ab + (size_t)sq * SEQ + sk) = v;
            }
            atomicAdd(&sexp[lr], lsum);
        }
    }
    __syncthreads();
    if (tid < 128)
        rowsum[((size_t)bh * SEQ + q0 + tid) * 8 + kb] = sexp[tid];
}

// =============================================================================
// Context GEMM + normalize: p = e * inv_rowsum; write p back to attn (final
// output) and compute ctx = p @ V per (b,h). BM=256, N=64, BK=32, 8 warps.
// =============================================================================
#define CSTR 36
#define VSTR 72
#define CP_U (256 * CSTR)
#define CV_U (32 * VSTR)
#define CTX_SMEM_BYTES ((2 * CP_U + 2 * CV_U) * 4)

__global__ __launch_bounds__(256)
void ctx_tf32_kernel(float* __restrict__ attn, const float* __restrict__ v,
                     const float* __restrict__ rowsum, float* __restrict__ ctx)
{
    extern __shared__ unsigned csm[];
    unsigned* Ps = csm;               // [2][CP_U]
    unsigned* Vs = csm + 2 * CP_U;    // [2][CV_U]

    const int tid  = threadIdx.x;
    const int wid  = tid >> 5;
    const int lane = tid & 31;
    const int gid  = lane >> 2;
    const int tig  = lane & 3;
    const int bh = blockIdx.y;
    const int q0 = blockIdx.x * 256;
    const int b = bh >> 4, h = bh & 15;

    float* pb = attn + (size_t)bh * SEQ * SEQ;
    const float* vb = v + (size_t)bh * SEQ * HDIM;

    const int prow = tid >> 3;            // 0..31 (+32*r)
    const int pc4  = (tid & 7) * 4;
    const int vrow = tid >> 4;            // 0..15 (+16*r)
    const int vc4  = (tid & 15) * 4;

    // per-thread row inverse sums (rows fixed across k-tiles)
    float inv[8];
#pragma unroll
    for (int r = 0; r < 8; r++) {
        size_t row = (size_t)bh * SEQ + q0 + prow + r * 32;
        const float4* ps = (const float4*)&rowsum[row * 8];
        float4 s0 = ps[0], s1 = ps[1];
        inv[r] = 1.0f / (s0.x + s0.y + s0.z + s0.w + s1.x + s1.y + s1.z + s1.w);
    }

    float acc[2][8][4];
#pragma unroll
    for (int mt = 0; mt < 2; mt++)
#pragma unroll
        for (int nt = 0; nt < 8; nt++)
#pragma unroll
            for (int r = 0; r < 4; r++) acc[mt][nt][r] = 0.0f;

    float4 p4[8], v4[2];
    // prologue: load tile 0, normalize, write back final attn
#pragma unroll
    for (int r = 0; r < 8; r++) {
        float* addr = pb + (size_t)(q0 + prow + r * 32) * SEQ + pc4;
        p4[r] = *(const float4*)addr;
        p4[r].x *= inv[r]; p4[r].y *= inv[r]; p4[r].z *= inv[r]; p4[r].w *= inv[r];
        *(float4*)addr = p4[r];
    }
#pragma unroll
    for (int r = 0; r < 2; r++)
        v4[r] = *(const float4*)(vb + (size_t)(vrow + r * 16) * HDIM + vc4);
#pragma unroll
    for (int r = 0; r < 8; r++) {
        unsigned* d = &Ps[(prow + r * 32) * CSTR + pc4];
        d[0] = f2tf(p4[r].x); d[1] = f2tf(p4[r].y); d[2] = f2tf(p4[r].z); d[3] = f2tf(p4[r].w);
    }
#pragma unroll
    for (int r = 0; r < 2; r++) {
        unsigned* e = &Vs[(vrow + r * 16) * VSTR + vc4];
        e[0] = f2tf(v4[r].x); e[1] = f2tf(v4[r].y); e[2] = f2tf(v4[r].z); e[3] = f2tf(v4[r].w);
    }

    int buf = 0;
    for (int kt = 0; kt < SEQ; kt += 32) {
        __syncthreads();
        const int more = (kt + 32 < SEQ);
        if (more) {
#pragma unroll
            for (int r = 0; r < 8; r++) {
                float* addr = pb + (size_t)(q0 + prow + r * 32) * SEQ + kt + 32 + pc4;
                p4[r] = *(const float4*)addr;
                p4[r].x *= inv[r]; p4[r].y *= inv[r]; p4[r].z *= inv[r]; p4[r].w *= inv[r];
                *(float4*)addr = p4[r];
            }
#pragma unroll
            for (int r = 0; r < 2; r++)
                v4[r] = *(const float4*)(vb + (size_t)(kt + 32 + vrow + r * 16) * HDIM + vc4);
        }

        const unsigned* Pb = &Ps[buf * CP_U];
        const unsigned* Vb = &Vs[buf * CV_U];
#pragma unroll
        for (int ks = 0; ks < 4; ks++) {
            unsigned af[2][4], bf[8][2];
#pragma unroll
            for (int mt = 0; mt < 2; mt++) {
                const unsigned* p  = &Pb[(wid * 32 + mt * 16 + gid) * CSTR + ks * 8 + tig];
                const unsigned* p2 = p + 8 * CSTR;
                af[mt][0] = p[0];  af[mt][2] = p[4];
                af[mt][1] = p2[0]; af[mt][3] = p2[4];
            }
#pragma unroll
            for (int nt = 0; nt < 8; nt++) {
                const unsigned* p = &Vb[(ks * 8 + tig) * VSTR + nt * 8 + gid];
                bf[nt][0] = p[0]; bf[nt][1] = p[4 * VSTR];
            }
#pragma unroll
            for (int mt = 0; mt < 2; mt++)
#pragma unroll
                for (int nt = 0; nt < 8; nt++)
                    mma8(acc[mt][nt], af[mt], bf[nt]);
        }

        if (more) {
            unsigned* Pn = &Ps[(buf ^ 1) * CP_U];
            unsigned* Vn = &Vs[(buf ^ 1) * CV_U];
#pragma unroll
            for (int r = 0; r < 8; r++) {
                unsigned* d = &Pn[(prow + r * 32) * CSTR + pc4];
                d[0] = f2tf(p4[r].x); d[1] = f2tf(p4[r].y); d[2] = f2tf(p4[r].z); d[3] = f2tf(p4[r].w);
            }
#pragma unroll
            for (int r = 0; r < 2; r++) {
                unsigned* e = &Vn[(vrow + r * 16) * VSTR + vc4];
                e[0] = f2tf(v4[r].x); e[1] = f2tf(v4[r].y); e[2] = f2tf(v4[r].z); e[3] = f2tf(v4[r].w);
            }
        }
        buf ^= 1;
    }

#pragma unroll
    for (int mt = 0; mt < 2; mt++) {
#pragma unroll
        for (int half = 0; half < 2; half++) {
            int qrow = q0 + wid * 32 + mt * 16 + gid + half * 8;
            float* crow = ctx + ((size_t)b * SEQ + qrow) * DMODEL + h * HDIM;
#pragma unroll
            for (int nt = 0; nt < 8; nt++) {
                int d = nt * 8 + tig * 2;
                float2 o;
                o.x = acc[mt][nt][half * 2 + 0];
                o.y = acc[mt][nt][half * 2 + 1];
                *(float2*)(crow + d) = o;
            }
        }
    }
}

// -------------------- launcher ----------------------------------------------
extern "C" void kernel_launch(void* const* d_in, const int* in_sizes, int n_in,
                              void* d_out, int out_size)
{
    const float* x  = (const float*)d_in[0];
    const float* Wq = (const float*)d_in[1];
    const float* bq = (const float*)d_in[2];
    const float* Wk = (const float*)d_in[3];
    const float* bk = (const float*)d_in[4];
    const float* Wv = (const float*)d_in[5];
    const float* bv = (const float*)d_in[6];
    const float* Wo = (const float*)d_in[7];
    const float* bo = (const float*)d_in[8];

    float* out_ptr  = (float*)d_out;                                   // [B,S,D]
    float* attn_ptr = (float*)d_out + (size_t)BATCH * SEQ * DMODEL;    // [B,H,S,S]

    float *qp, *kp, *vp, *cp, *rs;
    cudaGetSymbolAddress((void**)&qp, g_q);
    cudaGetSymbolAddress((void**)&kp, g_k);
    cudaGetSymbolAddress((void**)&vp, g_v);
    cudaGetSymbolAddress((void**)&cp, g_ctx);
    cudaGetSymbolAddress((void**)&rs, g_rowsum);

    cudaFuncSetAttribute(proj_tf32_kernel,
                         cudaFuncAttributeMaxDynamicSharedMemorySize, PROJ_SMEM_BYTES);
    cudaFuncSetAttribute(scores_tf32_kernel,
                         cudaFuncAttributeMaxDynamicSharedMemorySize, SCORES_SMEM_BYTES);
    cudaFuncSetAttribute(ctx_tf32_kernel,
                         cudaFuncAttributeMaxDynamicSharedMemorySize, CTX_SMEM_BYTES);

    dim3 blk(256);
    dim3 pgrid(DMODEL / 128, MTOT / 128);       // (8, 64)

    proj_tf32_kernel<<<pgrid, blk, PROJ_SMEM_BYTES>>>(x, Wq, bq, qp, 1);
    proj_tf32_kernel<<<pgrid, blk, PROJ_SMEM_BYTES>>>(x, Wk, bk, kp, 1);
    proj_tf32_kernel<<<pgrid, blk, PROJ_SMEM_BYTES>>>(x, Wv, bv, vp, 1);

    dim3 sgrid(SEQ / 128, SEQ / 128, BATCH * HEADS);   // (8, 8, 128)
    scores_tf32_kernel<<<sgrid, blk, SCORES_SMEM_BYTES>>>(qp, kp, attn_ptr, rs);

    dim3 cgrid(SEQ / 256, BATCH * HEADS);              // (4, 128)
    ctx_tf32_kernel<<<cgrid, blk, CTX_SMEM_BYTES>>>(attn_ptr, vp, rs, cp);

    proj_tf32_kernel<<<pgrid, blk, PROJ_SMEM_BYTES>>>(cp, Wo, bo, out_ptr, 0);
}

// round 7
// speedup vs baseline: 1.1551x; 1.1475x over previous
#include <cuda_runtime.h>
#include <math.h>

// Problem constants
#define BATCH  8
#define SEQ    1024
#define DMODEL 1024
#define HEADS  16
#define HDIM   64
#define MTOT   (BATCH * SEQ)          // 8192

// -------------------- scratch (__device__ globals; no allocs allowed) -------
__device__ float g_q[(size_t)BATCH * HEADS * SEQ * HDIM];   // [B,H,S,Hd] (tf32-rounded)
__device__ float g_k[(size_t)BATCH * HEADS * SEQ * HDIM];
__device__ float g_v[(size_t)BATCH * HEADS * SEQ * HDIM];
__device__ float g_ctx[(size_t)BATCH * SEQ * DMODEL];       // [B,S,D] (tf32-rounded)
__device__ float g_rowsum[(size_t)BATCH * HEADS * SEQ * 8]; // [row][kb] partial exp sums
__device__ float g_xr[(size_t)MTOT * DMODEL];               // rounded x
__device__ float g_wr[4][(size_t)DMODEL * DMODEL];          // rounded Wq,Wk,Wv,Wo

// -------------------- helpers ------------------------------------------------
__device__ __forceinline__ float rndf(float f) {   // round-to-nearest tf32, as fp32
    unsigned u;
    asm("cvt.rna.tf32.f32 %0, %1;" : "=r"(u) : "f"(f));
    return __uint_as_float(u);
}

__device__ __forceinline__ void cpa16(void* smem, const void* gmem) {
    unsigned sa = (unsigned)__cvta_generic_to_shared(smem);
    asm volatile("cp.async.cg.shared.global [%0], [%1], 16;\n" :: "r"(sa), "l"(gmem));
}
#define CP_COMMIT() asm volatile("cp.async.commit_group;\n")

// D = A(16x8,row)*B(8x8,col)+D, tf32 (operands pre-rounded -> truncation exact)
__device__ __forceinline__ void mma8(float* c, const unsigned* a, const unsigned* b) {
    asm volatile(
        "mma.sync.aligned.m16n8k8.row.col.f32.tf32.tf32.f32 "
        "{%0,%1,%2,%3}, {%4,%5,%6,%7}, {%8,%9}, {%0,%1,%2,%3};\n"
        : "+f"(c[0]), "+f"(c[1]), "+f"(c[2]), "+f"(c[3])
        : "r"(a[0]), "r"(a[1]), "r"(a[2]), "r"(a[3]), "r"(b[0]), "r"(b[1]));
}

// =============================================================================
// Elementwise tf32 rounding pre-pass (float4 vectorized)
// =============================================================================
__global__ __launch_bounds__(256)
void round_tf32_kernel(float* __restrict__ dst, const float* __restrict__ src, int n4)
{
    int i = blockIdx.x * blockDim.x + threadIdx.x;
    if (i < n4) {
        float4 v = ((const float4*)src)[i];
        v.x = rndf(v.x); v.y = rndf(v.y); v.z = rndf(v.z); v.w = rndf(v.w);
        ((float4*)dst)[i] = v;
    }
}

// =============================================================================
// Projection GEMM: C[M,1024] = A[M,1024] * W[1024,1024]^T + bias
// BM=128, BN=128, BK=32; 8 warps, warp tile 64x32. 3-stage cp.async pipeline.
// Inputs pre-rounded to tf32. split_heads outputs are re-rounded (consumed by
// later tf32 GEMMs); final out (split_heads=0) is exact fp32.
// =============================================================================
#define PSTR 36            // floats; 36%32==4 conflict-free; 144B row, 16B aligned
#define PBUF (128 * PSTR)
#define PNT  (DMODEL / 32)
#define PROJ_SMEM_BYTES (3 * 2 * PBUF * 4)   // 110592

__global__ __launch_bounds__(256, 2)
void proj_tf32_kernel(const float* __restrict__ A, const float* __restrict__ W,
                      const float* __restrict__ bias, float* __restrict__ C,
                      int split_heads)
{
    extern __shared__ float psm[];

    const int tid  = threadIdx.x;
    const int wid  = tid >> 5;
    const int lane = tid & 31;
    const int gid  = lane >> 2;
    const int tig  = lane & 3;
    const int m0 = blockIdx.y * 128;
    const int n0 = blockIdx.x * 128;
    const int wm = (wid >> 2) * 64;
    const int wn = (wid & 3) * 32;

    const int lrow = tid >> 3;
    const int lc4  = (tid & 7) * 4;

    float acc[4][4][4];
#pragma unroll
    for (int mt = 0; mt < 4; mt++)
#pragma unroll
        for (int nt = 0; nt < 4; nt++)
#pragma unroll
            for (int r = 0; r < 4; r++) acc[mt][nt][r] = 0.0f;

    auto load_tile = [&](int kt, int s) {
        float* As = psm + s * 2 * PBUF;
        float* Bs = As + PBUF;
#pragma unroll
        for (int r = 0; r < 4; r++) {
            int row = lrow + r * 32;
            cpa16(&As[row * PSTR + lc4], A + (size_t)(m0 + row) * DMODEL + kt + lc4);
            cpa16(&Bs[row * PSTR + lc4], W + (size_t)(n0 + row) * DMODEL + kt + lc4);
        }
    };

    load_tile(0, 0); CP_COMMIT();
    load_tile(32, 1); CP_COMMIT();

    for (int t = 0; t < PNT; t++) {
        if (t + 2 < PNT) { load_tile((t + 2) * 32, (t + 2) % 3); CP_COMMIT(); }
        if (t + 2 < PNT)      asm volatile("cp.async.wait_group 2;\n");
        else if (t + 1 < PNT) asm volatile("cp.async.wait_group 1;\n");
        else                  asm volatile("cp.async.wait_group 0;\n");
        __syncthreads();

        const unsigned* Ab = (const unsigned*)(psm + (t % 3) * 2 * PBUF);
        const unsigned* Bb = Ab + PBUF;
#pragma unroll
        for (int ks = 0; ks < 4; ks++) {
            unsigned af[4][4], bf[4][2];
#pragma unroll
            for (int mt = 0; mt < 4; mt++) {
                const unsigned* p  = &Ab[(wm + mt * 16 + gid) * PSTR + ks * 8 + tig];
                const unsigned* p2 = p + 8 * PSTR;
                af[mt][0] = p[0];  af[mt][2] = p[4];
                af[mt][1] = p2[0]; af[mt][3] = p2[4];
            }
#pragma unroll
            for (int nt = 0; nt < 4; nt++) {
                const unsigned* p = &Bb[(wn + nt * 8 + gid) * PSTR + ks * 8 + tig];
                bf[nt][0] = p[0]; bf[nt][1] = p[4];
            }
#pragma unroll
            for (int mt = 0; mt < 4; mt++)
#pragma unroll
                for (int nt = 0; nt < 4; nt++)
                    mma8(acc[mt][nt], af[mt], bf[nt]);
        }
        __syncthreads();
    }

#pragma unroll
    for (int mt = 0; mt < 4; mt++) {
#pragma unroll
        for (int half = 0; half < 2; half++) {
            int m  = m0 + wm + mt * 16 + gid + half * 8;
            int bb = m >> 10;
            int s  = m & 1023;
#pragma unroll
            for (int nt = 0; nt < 4; nt++) {
                int n = n0 + wn + nt * 8 + tig * 2;
                float2 v;
                v.x = acc[mt][nt][half * 2 + 0] + bias[n];
                v.y = acc[mt][nt][half * 2 + 1] + bias[n + 1];
                size_t idx;
                if (split_heads) {
                    v.x = rndf(v.x); v.y = rndf(v.y);   // consumed by tf32 GEMMs
                    int h = n >> 6, d = n & 63;
                    idx = ((((size_t)bb * HEADS + h) * SEQ + s) << 6) + d;
                } else {
                    idx = (size_t)m * DMODEL + n;
                }
                *(float2*)(C + idx) = v;
            }
        }
    }
}

// =============================================================================
// Scores: e = rnd(exp(Q.K/8)) UNNORMALIZED into attn, per-block row partial
// sums into g_rowsum[row][kb]. Tiles 128x128, K=64, per (b,h).
// =============================================================================
#define SSTR 68
#define SCORES_SMEM_BYTES (2 * 128 * SSTR * 4)   // 69632

__global__ __launch_bounds__(256, 2)
void scores_tf32_kernel(const float* __restrict__ q, const float* __restrict__ k,
                        float* __restrict__ attn, float* __restrict__ rowsum)
{
    extern __shared__ float ssm[];
    float* Qs = ssm;                 // [128][SSTR]
    float* Ks = ssm + 128 * SSTR;    // [128][SSTR]
    __shared__ float sexp[128];

    const int tid  = threadIdx.x;
    const int wid  = tid >> 5;
    const int lane = tid & 31;
    const int gid  = lane >> 2;
    const int tig  = lane & 3;
    const int bh = blockIdx.z;
    const int q0 = blockIdx.y * 128;
    const int k0 = blockIdx.x * 128;
    const int kb = blockIdx.x;
    const int wm = (wid >> 2) * 64;
    const int wn = (wid & 3) * 32;

    const float* qb = q + (size_t)bh * SEQ * HDIM;
    const float* kp = k + (size_t)bh * SEQ * HDIM;

#pragma unroll
    for (int r = 0; r < 8; r++) {
        int idx = tid + r * 256;
        int row = idx >> 4;
        int c4  = (idx & 15) * 4;
        cpa16(&Qs[row * SSTR + c4], qb + (size_t)(q0 + row) * HDIM + c4);
        cpa16(&Ks[row * SSTR + c4], kp + (size_t)(k0 + row) * HDIM + c4);
    }
    CP_COMMIT();
    if (tid < 128) sexp[tid] = 0.0f;
    asm volatile("cp.async.wait_group 0;\n");
    __syncthreads();

    float acc[4][4][4];
#pragma unroll
    for (int mt = 0; mt < 4; mt++)
#pragma unroll
        for (int nt = 0; nt < 4; nt++)
#pragma unroll
            for (int r = 0; r < 4; r++) acc[mt][nt][r] = 0.0f;

    const unsigned* Qu = (const unsigned*)Qs;
    const unsigned* Ku = (const unsigned*)Ks;
#pragma unroll
    for (int ks = 0; ks < 8; ks++) {
        unsigned af[4][4], bf[4][2];
#pragma unroll
        for (int mt = 0; mt < 4; mt++) {
            const unsigned* p  = &Qu[(wm + mt * 16 + gid) * SSTR + ks * 8 + tig];
            const unsigned* p2 = p + 8 * SSTR;
            af[mt][0] = p[0];  af[mt][2] = p[4];
            af[mt][1] = p2[0]; af[mt][3] = p2[4];
        }
#pragma unroll
        for (int nt = 0; nt < 4; nt++) {
            const unsigned* p = &Ku[(wn + nt * 8 + gid) * SSTR + ks * 8 + tig];
            bf[nt][0] = p[0]; bf[nt][1] = p[4];
        }
#pragma unroll
        for (int mt = 0; mt < 4; mt++)
#pragma unroll
            for (int nt = 0; nt < 4; nt++)
                mma8(acc[mt][nt], af[mt], bf[nt]);
    }

    float* ab = attn + (size_t)bh * SEQ * SEQ;
#pragma unroll
    for (int mt = 0; mt < 4; mt++) {
#pragma unroll
        for (int half = 0; half < 2; half++) {
            int lr = wm + mt * 16 + gid + half * 8;
            int sq = q0 + lr;
            float lsum = 0.0f;
#pragma unroll
            for (int nt = 0; nt < 4; nt++) {
                int sk = k0 + wn + nt * 8 + tig * 2;
                float2 v;
                v.x = rndf(__expf(acc[mt][nt][half * 2 + 0] * 0.125f));
                v.y = rndf(__expf(acc[mt][nt][half * 2 + 1] * 0.125f));
                lsum += v.x + v.y;
                *(float2*)(ab + (size_t)sq * SEQ + sk) = v;
            }
            lsum += __shfl_xor_sync(0xffffffffu, lsum, 1);
            lsum += __shfl_xor_sync(0xffffffffu, lsum, 2);
            if (tig == 0) atomicAdd(&sexp[lr], lsum);
        }
    }
    __syncthreads();
    if (tid < 128)
        rowsum[((size_t)bh * SEQ + q0 + tid) * 8 + kb] = sexp[tid];
}

// =============================================================================
// Context GEMM: acc = sum_k e[q,k]*V[k,d]; ctx = rnd(acc * inv) (normalize on
// OUTPUT). Writes final attn = e * inv from the smem tile.
// BM=256, N=64, BK=32; 8 warps; 2-stage cp.async.
// =============================================================================
#define CSTR 36
#define VSTR 72
#define CP_U (256 * CSTR)
#define CV_U (32 * VSTR)
#define CTX_SMEM_BYTES ((2 * CP_U + 2 * CV_U) * 4)   // 92160

__global__ __launch_bounds__(256, 2)
void ctx_tf32_kernel(float* __restrict__ attn, const float* __restrict__ v,
                     const float* __restrict__ rowsum, float* __restrict__ ctx)
{
    extern __shared__ float csm[];
    float* Ps = csm;               // [2][CP_U]
    float* Vs = csm + 2 * CP_U;    // [2][CV_U]

    const int tid  = threadIdx.x;
    const int wid  = tid >> 5;
    const int lane = tid & 31;
    const int gid  = lane >> 2;
    const int tig  = lane & 3;
    const int bh = blockIdx.y;
    const int q0 = blockIdx.x * 256;
    const int b = bh >> 4, h = bh & 15;

    float* pb = attn + (size_t)bh * SEQ * SEQ;
    const float* vb = v + (size_t)bh * SEQ * HDIM;

    const int prow = tid >> 3;
    const int pc4  = (tid & 7) * 4;
    const int vrow = tid >> 4;
    const int vc4  = (tid & 15) * 4;

    float inv[8];
#pragma unroll
    for (int r = 0; r < 8; r++) {
        size_t row = (size_t)bh * SEQ + q0 + prow + r * 32;
        const float4* ps = (const float4*)&rowsum[row * 8];
        float4 s0 = ps[0], s1 = ps[1];
        inv[r] = 1.0f / (s0.x + s0.y + s0.z + s0.w + s1.x + s1.y + s1.z + s1.w);
    }

    auto load_tile = [&](int kt, int s) {
        float* Pd = Ps + s * CP_U;
        float* Vd = Vs + s * CV_U;
#pragma unroll
        for (int r = 0; r < 8; r++) {
            int row = prow + r * 32;
            cpa16(&Pd[row * CSTR + pc4], pb + (size_t)(q0 + row) * SEQ + kt + pc4);
        }
#pragma unroll
        for (int r = 0; r < 2; r++) {
            int row = vrow + r * 16;
            cpa16(&Vd[row * VSTR + vc4], vb + (size_t)(kt + row) * HDIM + vc4);
        }
    };

    float acc[2][8][4];
#pragma unroll
    for (int mt = 0; mt < 2; mt++)
#pragma unroll
        for (int nt = 0; nt < 8; nt++)
#pragma unroll
            for (int r = 0; r < 4; r++) acc[mt][nt][r] = 0.0f;

    load_tile(0, 0); CP_COMMIT();

    int buf = 0;
    for (int kt = 0; kt < SEQ; kt += 32) {
        const int more = (kt + 32 < SEQ);
        if (more) { load_tile(kt + 32, buf ^ 1); CP_COMMIT(); }
        if (more) asm volatile("cp.async.wait_group 1;\n");
        else      asm volatile("cp.async.wait_group 0;\n");
        __syncthreads();

        const float* Pbf = Ps + buf * CP_U;
        // attn writeback: p = e * inv, from smem tile
#pragma unroll
        for (int r = 0; r < 8; r++) {
            int row = prow + r * 32;
            float4 e4 = *(const float4*)&Pbf[row * CSTR + pc4];
            e4.x *= inv[r]; e4.y *= inv[r]; e4.z *= inv[r]; e4.w *= inv[r];
            *(float4*)(pb + (size_t)(q0 + row) * SEQ + kt + pc4) = e4;
        }

        const unsigned* Pu = (const unsigned*)Pbf;
        const unsigned* Vu = (const unsigned*)(Vs + buf * CV_U);
#pragma unroll
        for (int ks = 0; ks < 4; ks++) {
            unsigned af[2][4], bf[8][2];
#pragma unroll
            for (int mt = 0; mt < 2; mt++) {
                const unsigned* p  = &Pu[(wid * 32 + mt * 16 + gid) * CSTR + ks * 8 + tig];
                const unsigned* p2 = p + 8 * CSTR;
                af[mt][0] = p[0];  af[mt][2] = p[4];
                af[mt][1] = p2[0]; af[mt][3] = p2[4];
            }
#pragma unroll
            for (int nt = 0; nt < 8; nt++) {
                const unsigned* p = &Vu[(ks * 8 + tig) * VSTR + nt * 8 + gid];
                bf[nt][0] = p[0]; bf[nt][1] = p[4 * VSTR];
            }
#pragma unroll
            for (int mt = 0; mt < 2; mt++)
#pragma unroll
                for (int nt = 0; nt < 8; nt++)
                    mma8(acc[mt][nt], af[mt], bf[nt]);
        }
        __syncthreads();
        buf ^= 1;
    }

#pragma unroll
    for (int mt = 0; mt < 2; mt++) {
#pragma unroll
        for (int half = 0; half < 2; half++) {
            int qrow = q0 + wid * 32 + mt * 16 + gid + half * 8;
            size_t grow = (size_t)bh * SEQ + qrow;
            const float4* ps = (const float4*)&rowsum[grow * 8];
            float4 s0 = ps[0], s1 = ps[1];
            float invE = 1.0f / (s0.x + s0.y + s0.z + s0.w + s1.x + s1.y + s1.z + s1.w);
            float* crow = ctx + ((size_t)b * SEQ + qrow) * DMODEL + h * HDIM;
#pragma unroll
            for (int nt = 0; nt < 8; nt++) {
                int d = nt * 8 + tig * 2;
                float2 o;
                o.x = rndf(acc[mt][nt][half * 2 + 0] * invE);
                o.y = rndf(acc[mt][nt][half * 2 + 1] * invE);
                *(float2*)(crow + d) = o;
            }
        }
    }
}

// -------------------- launcher ----------------------------------------------
extern "C" void kernel_launch(void* const* d_in, const int* in_sizes, int n_in,
                              void* d_out, int out_size)
{
    const float* x  = (const float*)d_in[0];
    const float* Wq = (const float*)d_in[1];
    const float* bq = (const float*)d_in[2];
    const float* Wk = (const float*)d_in[3];
    const float* bk = (const float*)d_in[4];
    const float* Wv = (const float*)d_in[5];
    const float* bv = (const float*)d_in[6];
    const float* Wo = (const float*)d_in[7];
    const float* bo = (const float*)d_in[8];

    float* out_ptr  = (float*)d_out;                                   // [B,S,D]
    float* attn_ptr = (float*)d_out + (size_t)BATCH * SEQ * DMODEL;    // [B,H,S,S]

    float *qp, *kp, *vp, *cp, *rs, *xr, *wr;
    cudaGetSymbolAddress((void**)&qp, g_q);
    cudaGetSymbolAddress((void**)&kp, g_k);
    cudaGetSymbolAddress((void**)&vp, g_v);
    cudaGetSymbolAddress((void**)&cp, g_ctx);
    cudaGetSymbolAddress((void**)&rs, g_rowsum);
    cudaGetSymbolAddress((void**)&xr, g_xr);
    cudaGetSymbolAddress((void**)&wr, g_wr);

    cudaFuncSetAttribute(proj_tf32_kernel,
                         cudaFuncAttributeMaxDynamicSharedMemorySize, PROJ_SMEM_BYTES);
    cudaFuncSetAttribute(scores_tf32_kernel,
                         cudaFuncAttributeMaxDynamicSharedMemorySize, SCORES_SMEM_BYTES);
    cudaFuncSetAttribute(ctx_tf32_kernel,
                         cudaFuncAttributeMaxDynamicSharedMemorySize, CTX_SMEM_BYTES);

    dim3 blk(256);

    // pre-round inputs to tf32-representable fp32
    const size_t WSZ = (size_t)DMODEL * DMODEL;
    int xn4 = (int)((size_t)MTOT * DMODEL / 4);
    int wn4 = (int)(WSZ / 4);
    round_tf32_kernel<<<(xn4 + 255) / 256, blk>>>(xr, x, xn4);
    round_tf32_kernel<<<(wn4 + 255) / 256, blk>>>(wr + 0 * WSZ, Wq, wn4);
    round_tf32_kernel<<<(wn4 + 255) / 256, blk>>>(wr + 1 * WSZ, Wk, wn4);
    round_tf32_kernel<<<(wn4 + 255) / 256, blk>>>(wr + 2 * WSZ, Wv, wn4);
    round_tf32_kernel<<<(wn4 + 255) / 256, blk>>>(wr + 3 * WSZ, Wo, wn4);

    dim3 pgrid(DMODEL / 128, MTOT / 128);       // (8, 64)
    proj_tf32_kernel<<<pgrid, blk, PROJ_SMEM_BYTES>>>(xr, wr + 0 * WSZ, bq, qp, 1);
    proj_tf32_kernel<<<pgrid, blk, PROJ_SMEM_BYTES>>>(xr, wr + 1 * WSZ, bk, kp, 1);
    proj_tf32_kernel<<<pgrid, blk, PROJ_SMEM_BYTES>>>(xr, wr + 2 * WSZ, bv, vp, 1);

    dim3 sgrid(SEQ / 128, SEQ / 128, BATCH * HEADS);   // (8, 8, 128)
    scores_tf32_kernel<<<sgrid, blk, SCORES_SMEM_BYTES>>>(qp, kp, attn_ptr, rs);

    dim3 cgrid(SEQ / 256, BATCH * HEADS);              // (4, 128)
    ctx_tf32_kernel<<<cgrid, blk, CTX_SMEM_BYTES>>>(attn_ptr, vp, rs, cp);

    proj_tf32_kernel<<<pgrid, blk, PROJ_SMEM_BYTES>>>(cp, wr + 3 * WSZ, bo, out_ptr, 0);
}